// round 14
// baseline (speedup 1.0000x reference)
#include <cuda_runtime.h>
#include <cuda_fp16.h>
#include <cstdint>

#define N_BUILD 1048576
#define N_CABLE 50000
#define N_TRANS 2000
#define D 128
#define TILE_M 256   // 8 warps x 32 rows

// ---------------- device scratch (no allocations allowed) ----------------
__device__ float g_sum_c[N_CABLE * D];
__device__ int   g_cnt_c[N_CABLE];
__device__ float g_sum_t[N_TRANS * D];
__device__ int   g_cnt_t[N_TRANS];

// SMEM: weight tiles [n=128][k=128] fp16, row stride 256B, XOR-swizzled 16B chunks.
#define OFF_WAH 0
#define OFF_WBH 32768
#define OFF_BA  65536
#define OFF_BB  (OFF_BA + 512)
#define SMEM_DYN (OFF_BB + 512 + 1024)

static __device__ __forceinline__ uint32_t smem_u32(const void* p) {
    uint32_t a;
    asm("{ .reg .u64 t; cvta.to.shared.u64 t, %1; cvt.u32.u64 %0, t; }" : "=r"(a) : "l"(p));
    return a;
}
static __device__ __forceinline__ uint32_t pk_h2(float a, float b) {
    __half2 h = __floats2half2_rn(a, b);
    return *(uint32_t*)&h;
}
static __device__ __forceinline__ void ldsm4(uint32_t* r, uint32_t addr) {
    asm volatile("ldmatrix.sync.aligned.m8n8.x4.shared.b16 {%0,%1,%2,%3}, [%4];"
                 : "=r"(r[0]), "=r"(r[1]), "=r"(r[2]), "=r"(r[3]) : "r"(addr));
}
static __device__ __forceinline__ void mma16816(float* c, const uint32_t* a, uint32_t b0, uint32_t b1) {
    asm volatile("mma.sync.aligned.m16n8k16.row.col.f32.f16.f16.f32 "
                 "{%0,%1,%2,%3}, {%4,%5,%6,%7}, {%8,%9}, {%0,%1,%2,%3};"
                 : "+f"(c[0]), "+f"(c[1]), "+f"(c[2]), "+f"(c[3])
                 : "r"(a[0]), "r"(a[1]), "r"(a[2]), "r"(a[3]), "r"(b0), "r"(b1));
}
static __device__ __forceinline__ void red_add_v2(float* p, float a, float b) {
    asm volatile("red.global.add.v2.f32 [%0], {%1, %2};" :: "l"(p), "f"(a), "f"(b) : "memory");
}

// ---------------- zero scratch ----------------
__global__ void zero_kernel() {
    int stride = gridDim.x * blockDim.x;
    int t = blockIdx.x * blockDim.x + threadIdx.x;
    float4 z = make_float4(0.f, 0.f, 0.f, 0.f);
    for (int i = t; i < N_CABLE * D / 4; i += stride) ((float4*)g_sum_c)[i] = z;
    for (int i = t; i < N_TRANS * D / 4; i += stride) ((float4*)g_sum_t)[i] = z;
    for (int i = t; i < N_CABLE; i += stride) g_cnt_c[i] = 0;
    for (int i = t; i < N_TRANS; i += stride) g_cnt_t[i] = 0;
}

// ---------------- fused 2-layer MLP + scatter-add, HMMA fp16, M=32/warp ----------------
template<int MODE>
__global__ __launch_bounds__(256, 1)
void mlp_pool(int nrows, int ntiles,
              const float* __restrict__ xin, const int* __restrict__ idx,
              const float* __restrict__ wA, const float* __restrict__ bA,
              const float* __restrict__ wB, const float* __restrict__ bB,
              float* __restrict__ out_cable) {
    extern __shared__ char smraw[];
    char* sm = (char*)(((uintptr_t)smraw + 1023) & ~(uintptr_t)1023);
    const uint32_t smU = smem_u32(sm);
    float* bAs = (float*)(sm + OFF_BA);
    float* bBs = (float*)(sm + OFF_BB);

    const int tid  = threadIdx.x;
    const int wid  = tid >> 5;
    const int lane = tid & 31;
    const int q    = lane & 3;
    const int rq   = lane >> 2;

    // ---- convert weights to fp16 (RN), swizzle into smem (once per CTA) ----
    for (int i = tid; i < 2 * 128 * 16; i += 256) {
        int m  = i >> 11;
        int r  = (i >> 4) & 127;
        int kc = i & 15;
        const float* src = (m ? wB : wA) + r * 128 + kc * 8;
        float4 f0 = *(const float4*)(src);
        float4 f1 = *(const float4*)(src + 4);
        uint4 hi;
        hi.x = pk_h2(f0.x, f0.y); hi.y = pk_h2(f0.z, f0.w);
        hi.z = pk_h2(f1.x, f1.y); hi.w = pk_h2(f1.z, f1.w);
        uint32_t off = (uint32_t)(r * 256 + ((kc ^ (r & 7)) << 4));
        *(uint4*)(sm + (m ? OFF_WBH : OFF_WAH) + off) = hi;
    }
    for (int i = tid; i < D; i += 256) { bAs[i] = bA[i]; bBs[i] = bB[i]; }
    __syncthreads();

    float* dst = MODE ? g_sum_t : g_sum_c;
    int*   cnt = MODE ? g_cnt_t : g_cnt_c;

    const int browX = ((lane >> 4) << 3) + (lane & 7);
    const int kb    = (lane >> 3) & 1;

    for (int t = blockIdx.x; t < ntiles; t += gridDim.x) {
        const int base = t * TILE_M + wid * 32;
        int rA[2], rB[2], cidA[2], cidB[2];
        float rcA[2], rcB[2];
        #pragma unroll
        for (int h = 0; h < 2; h++) {
            rA[h] = base + 16 * h + rq;
            rB[h] = rA[h] + 8;
            if (MODE == 0) {
                cidA[h] = idx[rA[h]];
                cidB[h] = idx[rB[h]];
            } else {
                cidA[h] = (rA[h] < nrows) ? idx[rA[h]] : -1;
                cidB[h] = (rB[h] < nrows) ? idx[rB[h]] : -1;
                rcA[h] = (rA[h] < nrows) ? 1.0f / fmaxf((float)g_cnt_c[rA[h]], 1.0f) : 0.f;
                rcB[h] = (rB[h] < nrows) ? 1.0f / fmaxf((float)g_cnt_c[rB[h]], 1.0f) : 0.f;
            }
        }

        // ================= layer 1 (s-outer, full acc, bias-initialized) =================
        float acc[2][16][4];
        #pragma unroll
        for (int j = 0; j < 16; j++) {
            int col0 = 8 * j + 2 * q;
            float b0 = bAs[col0], b1 = bAs[col0 + 1];
            #pragma unroll
            for (int h = 0; h < 2; h++) {
                acc[h][j][0] = b0; acc[h][j][1] = b1;
                acc[h][j][2] = b0; acc[h][j][3] = b1;
            }
        }

        #pragma unroll
        for (int s = 0; s < 8; s++) {
            const int k0 = 16 * s + 2 * q;
            uint32_t ah[2][4];
            #pragma unroll
            for (int h = 0; h < 2; h++) {
                float2 va, vb, vc, vd;
                if (MODE == 0) {
                    const float* p1 = xin + (size_t)rA[h] * D;
                    const float* p2 = xin + (size_t)rB[h] * D;
                    va = *(const float2*)(p1 + k0);
                    vb = *(const float2*)(p2 + k0);
                    vc = *(const float2*)(p1 + k0 + 8);
                    vd = *(const float2*)(p2 + k0 + 8);
                } else {
                    va = vb = vc = vd = make_float2(0.f, 0.f);
                    if (cidA[h] >= 0) {
                        const float* p1 = g_sum_c + (size_t)rA[h] * D;
                        float2 v = *(const float2*)(p1 + k0);
                        va.x = v.x * rcA[h]; va.y = v.y * rcA[h];
                        float2 w = *(const float2*)(p1 + k0 + 8);
                        vc.x = w.x * rcA[h]; vc.y = w.y * rcA[h];
                        *(float2*)(out_cable + (size_t)rA[h] * D + k0) = va;
                        *(float2*)(out_cable + (size_t)rA[h] * D + k0 + 8) = vc;
                    }
                    if (cidB[h] >= 0) {
                        const float* p2 = g_sum_c + (size_t)rB[h] * D;
                        float2 v = *(const float2*)(p2 + k0);
                        vb.x = v.x * rcB[h]; vb.y = v.y * rcB[h];
                        float2 w = *(const float2*)(p2 + k0 + 8);
                        vd.x = w.x * rcB[h]; vd.y = w.y * rcB[h];
                        *(float2*)(out_cable + (size_t)rB[h] * D + k0) = vb;
                        *(float2*)(out_cable + (size_t)rB[h] * D + k0 + 8) = vd;
                    }
                }
                ah[h][0] = pk_h2(va.x, va.y);
                ah[h][1] = pk_h2(vb.x, vb.y);
                ah[h][2] = pk_h2(vc.x, vc.y);
                ah[h][3] = pk_h2(vd.x, vd.y);
            }
            // double-buffered ldsm over g
            uint32_t bh[2][4];
            {
                int brow = browX;
                ldsm4(bh[0], smU + (uint32_t)(brow * 256 + (((2 * s + kb) ^ (brow & 7)) << 4)) + OFF_WAH);
            }
            #pragma unroll
            for (int g = 0; g < 8; g++) {
                if (g < 7) {
                    int brow = 16 * (g + 1) + browX;
                    ldsm4(bh[(g + 1) & 1], smU + (uint32_t)(brow * 256 + (((2 * s + kb) ^ (brow & 7)) << 4)) + OFF_WAH);
                }
                const uint32_t* bb = bh[g & 1];
                #pragma unroll
                for (int h = 0; h < 2; h++) {
                    mma16816(acc[h][2*g],   ah[h], bb[0], bb[1]);
                    mma16816(acc[h][2*g+1], ah[h], bb[2], bb[3]);
                }
            }
        }

        // ---- transition: H = relu(acc) -> packed fp16 A fragments ----
        uint32_t AH[2][32];
        #pragma unroll
        for (int h = 0; h < 2; h++) {
            #pragma unroll
            for (int j = 0; j < 16; j++) {
                float v0 = fmaxf(acc[h][j][0], 0.f);
                float v1 = fmaxf(acc[h][j][1], 0.f);
                float v2 = fmaxf(acc[h][j][2], 0.f);
                float v3 = fmaxf(acc[h][j][3], 0.f);
                int i0 = (j >> 1) * 4 + (j & 1) * 2;
                AH[h][i0]     = pk_h2(v0, v1);
                AH[h][i0 + 1] = pk_h2(v2, v3);
            }
        }

        // ================= layer 2 (s-outer, full acc reused, bias-initialized) =================
        #pragma unroll
        for (int j = 0; j < 16; j++) {
            int col0 = 8 * j + 2 * q;
            float b0 = bBs[col0], b1 = bBs[col0 + 1];
            #pragma unroll
            for (int h = 0; h < 2; h++) {
                acc[h][j][0] = b0; acc[h][j][1] = b1;
                acc[h][j][2] = b0; acc[h][j][3] = b1;
            }
        }

        #pragma unroll
        for (int s = 0; s < 8; s++) {
            // double-buffered ldsm over g
            uint32_t bh[2][4];
            {
                int brow = browX;
                ldsm4(bh[0], smU + (uint32_t)(brow * 256 + (((2 * s + kb) ^ (brow & 7)) << 4)) + OFF_WBH);
            }
            #pragma unroll
            for (int g = 0; g < 8; g++) {
                if (g < 7) {
                    int brow = 16 * (g + 1) + browX;
                    ldsm4(bh[(g + 1) & 1], smU + (uint32_t)(brow * 256 + (((2 * s + kb) ^ (brow & 7)) << 4)) + OFF_WBH);
                }
                const uint32_t* bb = bh[g & 1];
                #pragma unroll
                for (int h = 0; h < 2; h++) {
                    mma16816(acc[h][2*g],   &AH[h][4*s], bb[0], bb[1]);
                    mma16816(acc[h][2*g+1], &AH[h][4*s], bb[2], bb[3]);
                }
            }
        }

        // ---- scatter all 128 cols: every lane red.v2 for both of its rows ----
        #pragma unroll
        for (int j = 0; j < 16; j++) {
            int col0 = 8 * j + 2 * q;
            #pragma unroll
            for (int h = 0; h < 2; h++) {
                if (cidA[h] >= 0)
                    red_add_v2(dst + (size_t)cidA[h] * D + col0, acc[h][j][0], acc[h][j][1]);
                if (cidB[h] >= 0)
                    red_add_v2(dst + (size_t)cidB[h] * D + col0, acc[h][j][2], acc[h][j][3]);
            }
        }
        if (q == 0) {
            #pragma unroll
            for (int h = 0; h < 2; h++) {
                if (cidA[h] >= 0) atomicAdd(cnt + cidA[h], 1);
                if (cidB[h] >= 0) atomicAdd(cnt + cidB[h], 1);
            }
        }
    }
}

// ---------------- finalize: x_trans = g_sum_t / max(cnt,1) ----------------
__global__ void finalize_trans(float* __restrict__ out_trans) {
    int i = blockIdx.x * blockDim.x + threadIdx.x;
    if (i < N_TRANS * D) {
        int row = i >> 7;
        float cnt = fmaxf((float)g_cnt_t[row], 1.0f);
        out_trans[i] = g_sum_t[i] / cnt;
    }
}

extern "C" void kernel_launch(void* const* d_in, const int* in_sizes, int n_in,
                              void* d_out, int out_size) {
    const float* x   = (const float*)d_in[0];
    const int*   abc = (const int*)d_in[1];
    const int*   act = (const int*)d_in[2];
    const float* w1  = (const float*)d_in[3];
    const float* b1  = (const float*)d_in[4];
    const float* w2  = (const float*)d_in[5];
    const float* b2  = (const float*)d_in[6];
    const float* w3  = (const float*)d_in[7];
    const float* b3  = (const float*)d_in[8];
    const float* w4  = (const float*)d_in[9];
    const float* b4  = (const float*)d_in[10];

    float* out = (float*)d_out;
    float* out_cable = out;                        // [N_CABLE, D]
    float* out_trans = out + (size_t)N_CABLE * D;  // [N_TRANS, D]

    cudaFuncSetAttribute(mlp_pool<0>, cudaFuncAttributeMaxDynamicSharedMemorySize, SMEM_DYN);
    cudaFuncSetAttribute(mlp_pool<1>, cudaFuncAttributeMaxDynamicSharedMemorySize, SMEM_DYN);

    const int ntA = N_BUILD / TILE_M;
    const int ntB = (N_CABLE + TILE_M - 1) / TILE_M;

    zero_kernel<<<1024, 256>>>();
    mlp_pool<0><<<152, 256, SMEM_DYN>>>(N_BUILD, ntA, x, abc, w1, b1, w2, b2, nullptr);
    mlp_pool<1><<<152, 256, SMEM_DYN>>>(N_CABLE, ntB, nullptr, act, w3, b3, w4, b4, out_cable);
    finalize_trans<<<(N_TRANS * D + 255) / 256, 256>>>(out_trans);
    (void)in_sizes; (void)n_in; (void)out_size;
}

// round 15
// speedup vs baseline: 1.1171x; 1.1171x over previous
#include <cuda_runtime.h>
#include <cuda_fp16.h>
#include <cstdint>

#define N_BUILD 1048576
#define N_CABLE 50000
#define N_TRANS 2000
#define D 128
#define TILE_M 256   // 8 warps x 32 rows

// ---------------- device scratch (no allocations allowed) ----------------
__device__ float g_sum_c[N_CABLE * D];
__device__ int   g_cnt_c[N_CABLE];
__device__ float g_sum_t[N_TRANS * D];
__device__ int   g_cnt_t[N_TRANS];

// SMEM: weight tiles [n=128][k=128] fp16, row stride 256B, XOR-swizzled 16B chunks.
#define OFF_WAH 0
#define OFF_WBH 32768
#define OFF_BA  65536
#define OFF_BB  (OFF_BA + 512)
#define SMEM_DYN (OFF_BB + 512 + 1024)

static __device__ __forceinline__ uint32_t smem_u32(const void* p) {
    uint32_t a;
    asm("{ .reg .u64 t; cvta.to.shared.u64 t, %1; cvt.u32.u64 %0, t; }" : "=r"(a) : "l"(p));
    return a;
}
static __device__ __forceinline__ uint32_t pk_h2(float a, float b) {
    __half2 h = __floats2half2_rn(a, b);
    return *(uint32_t*)&h;
}
static __device__ __forceinline__ void ldsm4(uint32_t* r, uint32_t addr) {
    asm volatile("ldmatrix.sync.aligned.m8n8.x4.shared.b16 {%0,%1,%2,%3}, [%4];"
                 : "=r"(r[0]), "=r"(r[1]), "=r"(r[2]), "=r"(r[3]) : "r"(addr));
}
static __device__ __forceinline__ void mma16816(float* c, const uint32_t* a, uint32_t b0, uint32_t b1) {
    asm volatile("mma.sync.aligned.m16n8k16.row.col.f32.f16.f16.f32 "
                 "{%0,%1,%2,%3}, {%4,%5,%6,%7}, {%8,%9}, {%0,%1,%2,%3};"
                 : "+f"(c[0]), "+f"(c[1]), "+f"(c[2]), "+f"(c[3])
                 : "r"(a[0]), "r"(a[1]), "r"(a[2]), "r"(a[3]), "r"(b0), "r"(b1));
}
static __device__ __forceinline__ void red_add_v2(float* p, float a, float b) {
    asm volatile("red.global.add.v2.f32 [%0], {%1, %2};" :: "l"(p), "f"(a), "f"(b) : "memory");
}

// ---------------- zero scratch ----------------
__global__ void zero_kernel() {
    int stride = gridDim.x * blockDim.x;
    int t = blockIdx.x * blockDim.x + threadIdx.x;
    float4 z = make_float4(0.f, 0.f, 0.f, 0.f);
    for (int i = t; i < N_CABLE * D / 4; i += stride) ((float4*)g_sum_c)[i] = z;
    for (int i = t; i < N_TRANS * D / 4; i += stride) ((float4*)g_sum_t)[i] = z;
    for (int i = t; i < N_CABLE; i += stride) g_cnt_c[i] = 0;
    for (int i = t; i < N_TRANS; i += stride) g_cnt_t[i] = 0;
}

// ---------------- fused 2-layer MLP + scatter-add, HMMA fp16, M=32/warp ----------------
template<int MODE>
__global__ __launch_bounds__(256, 1)
void mlp_pool(int nrows, int ntiles,
              const float* __restrict__ xin, const int* __restrict__ idx,
              const float* __restrict__ wA, const float* __restrict__ bA,
              const float* __restrict__ wB, const float* __restrict__ bB,
              float* __restrict__ out_cable) {
    extern __shared__ char smraw[];
    char* sm = (char*)(((uintptr_t)smraw + 1023) & ~(uintptr_t)1023);
    const uint32_t smU = smem_u32(sm);
    float* bAs = (float*)(sm + OFF_BA);
    float* bBs = (float*)(sm + OFF_BB);

    const int tid  = threadIdx.x;
    const int wid  = tid >> 5;
    const int lane = tid & 31;
    const int q    = lane & 3;
    const int rq   = lane >> 2;

    // ---- convert weights to fp16 (RN), swizzle into smem (once per CTA) ----
    for (int i = tid; i < 2 * 128 * 16; i += 256) {
        int m  = i >> 11;
        int r  = (i >> 4) & 127;
        int kc = i & 15;
        const float* src = (m ? wB : wA) + r * 128 + kc * 8;
        float4 f0 = *(const float4*)(src);
        float4 f1 = *(const float4*)(src + 4);
        uint4 hi;
        hi.x = pk_h2(f0.x, f0.y); hi.y = pk_h2(f0.z, f0.w);
        hi.z = pk_h2(f1.x, f1.y); hi.w = pk_h2(f1.z, f1.w);
        uint32_t off = (uint32_t)(r * 256 + ((kc ^ (r & 7)) << 4));
        *(uint4*)(sm + (m ? OFF_WBH : OFF_WAH) + off) = hi;
    }
    for (int i = tid; i < D; i += 256) { bAs[i] = bA[i]; bBs[i] = bB[i]; }
    __syncthreads();

    float* dst = MODE ? g_sum_t : g_sum_c;
    int*   cnt = MODE ? g_cnt_t : g_cnt_c;

    const int browX = ((lane >> 4) << 3) + (lane & 7);
    const int kb    = (lane >> 3) & 1;

    for (int t = blockIdx.x; t < ntiles; t += gridDim.x) {
        const int base = t * TILE_M + wid * 32;
        int rA[2], rB[2], cidA[2], cidB[2];
        float rcA[2], rcB[2];
        #pragma unroll
        for (int h = 0; h < 2; h++) {
            rA[h] = base + 16 * h + rq;
            rB[h] = rA[h] + 8;
            if (MODE == 0) {
                cidA[h] = idx[rA[h]];
                cidB[h] = idx[rB[h]];
            } else {
                cidA[h] = (rA[h] < nrows) ? idx[rA[h]] : -1;
                cidB[h] = (rB[h] < nrows) ? idx[rB[h]] : -1;
                rcA[h] = (rA[h] < nrows) ? 1.0f / fmaxf((float)g_cnt_c[rA[h]], 1.0f) : 0.f;
                rcB[h] = (rB[h] < nrows) ? 1.0f / fmaxf((float)g_cnt_c[rB[h]], 1.0f) : 0.f;
            }
        }

        // ================= layer 1 (s-outer, full acc, bias-initialized) =================
        float acc[2][16][4];
        #pragma unroll
        for (int j = 0; j < 16; j++) {
            int col0 = 8 * j + 2 * q;
            float b0 = bAs[col0], b1 = bAs[col0 + 1];
            #pragma unroll
            for (int h = 0; h < 2; h++) {
                acc[h][j][0] = b0; acc[h][j][1] = b1;
                acc[h][j][2] = b0; acc[h][j][3] = b1;
            }
        }

        #pragma unroll
        for (int s = 0; s < 8; s++) {
            const int k0 = 16 * s + 2 * q;
            uint32_t ah[2][4];
            #pragma unroll
            for (int h = 0; h < 2; h++) {
                float2 va, vb, vc, vd;
                if (MODE == 0) {
                    const float* p1 = xin + (size_t)rA[h] * D;
                    const float* p2 = xin + (size_t)rB[h] * D;
                    va = *(const float2*)(p1 + k0);
                    vb = *(const float2*)(p2 + k0);
                    vc = *(const float2*)(p1 + k0 + 8);
                    vd = *(const float2*)(p2 + k0 + 8);
                } else {
                    va = vb = vc = vd = make_float2(0.f, 0.f);
                    if (cidA[h] >= 0) {
                        const float* p1 = g_sum_c + (size_t)rA[h] * D;
                        float2 v = *(const float2*)(p1 + k0);
                        va.x = v.x * rcA[h]; va.y = v.y * rcA[h];
                        float2 w = *(const float2*)(p1 + k0 + 8);
                        vc.x = w.x * rcA[h]; vc.y = w.y * rcA[h];
                        *(float2*)(out_cable + (size_t)rA[h] * D + k0) = va;
                        *(float2*)(out_cable + (size_t)rA[h] * D + k0 + 8) = vc;
                    }
                    if (cidB[h] >= 0) {
                        const float* p2 = g_sum_c + (size_t)rB[h] * D;
                        float2 v = *(const float2*)(p2 + k0);
                        vb.x = v.x * rcB[h]; vb.y = v.y * rcB[h];
                        float2 w = *(const float2*)(p2 + k0 + 8);
                        vd.x = w.x * rcB[h]; vd.y = w.y * rcB[h];
                        *(float2*)(out_cable + (size_t)rB[h] * D + k0) = vb;
                        *(float2*)(out_cable + (size_t)rB[h] * D + k0 + 8) = vd;
                    }
                }
                ah[h][0] = pk_h2(va.x, va.y);
                ah[h][1] = pk_h2(vb.x, vb.y);
                ah[h][2] = pk_h2(vc.x, vc.y);
                ah[h][3] = pk_h2(vd.x, vd.y);
            }
            // double-buffered ldsm over g
            uint32_t bh[2][4];
            {
                int brow = browX;
                ldsm4(bh[0], smU + (uint32_t)(brow * 256 + (((2 * s + kb) ^ (brow & 7)) << 4)) + OFF_WAH);
            }
            #pragma unroll
            for (int g = 0; g < 8; g++) {
                if (g < 7) {
                    int brow = 16 * (g + 1) + browX;
                    ldsm4(bh[(g + 1) & 1], smU + (uint32_t)(brow * 256 + (((2 * s + kb) ^ (brow & 7)) << 4)) + OFF_WAH);
                }
                const uint32_t* bb = bh[g & 1];
                #pragma unroll
                for (int h = 0; h < 2; h++) {
                    mma16816(acc[h][2*g],   ah[h], bb[0], bb[1]);
                    mma16816(acc[h][2*g+1], ah[h], bb[2], bb[3]);
                }
            }
        }

        // ---- transition: H = relu(acc) -> packed fp16 A fragments ----
        uint32_t AH[2][32];
        #pragma unroll
        for (int h = 0; h < 2; h++) {
            #pragma unroll
            for (int j = 0; j < 16; j++) {
                float v0 = fmaxf(acc[h][j][0], 0.f);
                float v1 = fmaxf(acc[h][j][1], 0.f);
                float v2 = fmaxf(acc[h][j][2], 0.f);
                float v3 = fmaxf(acc[h][j][3], 0.f);
                int i0 = (j >> 1) * 4 + (j & 1) * 2;
                AH[h][i0]     = pk_h2(v0, v1);
                AH[h][i0 + 1] = pk_h2(v2, v3);
            }
        }

        // ================= layer 2 (g-pair-outer: 8 indep chains, scatter per pair) =================
        #pragma unroll
        for (int gg = 0; gg < 4; gg++) {
            float a2[2][2][2][4];   // [gp][h][tt][e]
            #pragma unroll
            for (int gp = 0; gp < 2; gp++) {
                int g = 2 * gg + gp;
                #pragma unroll
                for (int tt = 0; tt < 2; tt++) {
                    int col0 = 16 * g + 8 * tt + 2 * q;
                    float b0 = bBs[col0], b1 = bBs[col0 + 1];
                    #pragma unroll
                    for (int h = 0; h < 2; h++) {
                        a2[gp][h][tt][0] = b0; a2[gp][h][tt][1] = b1;
                        a2[gp][h][tt][2] = b0; a2[gp][h][tt][3] = b1;
                    }
                }
            }

            // double-buffered ldsm over s, one per g of the pair
            uint32_t bh[2][2][4];   // [buf][gp]
            #pragma unroll
            for (int gp = 0; gp < 2; gp++) {
                int brow = 16 * (2 * gg + gp) + browX;
                ldsm4(bh[0][gp], smU + (uint32_t)(brow * 256 + ((kb ^ (brow & 7)) << 4)) + OFF_WBH);
            }
            #pragma unroll
            for (int s = 0; s < 8; s++) {
                if (s < 7) {
                    #pragma unroll
                    for (int gp = 0; gp < 2; gp++) {
                        int brow = 16 * (2 * gg + gp) + browX;
                        ldsm4(bh[(s + 1) & 1][gp],
                              smU + (uint32_t)(brow * 256 + (((2 * (s + 1) + kb) ^ (brow & 7)) << 4)) + OFF_WBH);
                    }
                }
                #pragma unroll
                for (int gp = 0; gp < 2; gp++) {
                    const uint32_t* bb = bh[s & 1][gp];
                    #pragma unroll
                    for (int h = 0; h < 2; h++) {
                        mma16816(a2[gp][h][0], &AH[h][4*s], bb[0], bb[1]);
                        mma16816(a2[gp][h][1], &AH[h][4*s], bb[2], bb[3]);
                    }
                }
            }
            // scatter cols [32gg, 32gg+32): every lane red.v2 for both of its rows
            #pragma unroll
            for (int gp = 0; gp < 2; gp++) {
                int g = 2 * gg + gp;
                #pragma unroll
                for (int h = 0; h < 2; h++) {
                    #pragma unroll
                    for (int tt = 0; tt < 2; tt++) {
                        int col0 = 16 * g + 8 * tt + 2 * q;
                        if (cidA[h] >= 0)
                            red_add_v2(dst + (size_t)cidA[h] * D + col0, a2[gp][h][tt][0], a2[gp][h][tt][1]);
                        if (cidB[h] >= 0)
                            red_add_v2(dst + (size_t)cidB[h] * D + col0, a2[gp][h][tt][2], a2[gp][h][tt][3]);
                    }
                }
            }
        }
        if (q == 0) {
            #pragma unroll
            for (int h = 0; h < 2; h++) {
                if (cidA[h] >= 0) atomicAdd(cnt + cidA[h], 1);
                if (cidB[h] >= 0) atomicAdd(cnt + cidB[h], 1);
            }
        }
    }
}

// ---------------- finalize: x_trans = g_sum_t / max(cnt,1) ----------------
__global__ void finalize_trans(float* __restrict__ out_trans) {
    int i = blockIdx.x * blockDim.x + threadIdx.x;
    if (i < N_TRANS * D) {
        int row = i >> 7;
        float cnt = fmaxf((float)g_cnt_t[row], 1.0f);
        out_trans[i] = g_sum_t[i] / cnt;
    }
}

extern "C" void kernel_launch(void* const* d_in, const int* in_sizes, int n_in,
                              void* d_out, int out_size) {
    const float* x   = (const float*)d_in[0];
    const int*   abc = (const int*)d_in[1];
    const int*   act = (const int*)d_in[2];
    const float* w1  = (const float*)d_in[3];
    const float* b1  = (const float*)d_in[4];
    const float* w2  = (const float*)d_in[5];
    const float* b2  = (const float*)d_in[6];
    const float* w3  = (const float*)d_in[7];
    const float* b3  = (const float*)d_in[8];
    const float* w4  = (const float*)d_in[9];
    const float* b4  = (const float*)d_in[10];

    float* out = (float*)d_out;
    float* out_cable = out;                        // [N_CABLE, D]
    float* out_trans = out + (size_t)N_CABLE * D;  // [N_TRANS, D]

    cudaFuncSetAttribute(mlp_pool<0>, cudaFuncAttributeMaxDynamicSharedMemorySize, SMEM_DYN);
    cudaFuncSetAttribute(mlp_pool<1>, cudaFuncAttributeMaxDynamicSharedMemorySize, SMEM_DYN);

    const int ntA = N_BUILD / TILE_M;
    const int ntB = (N_CABLE + TILE_M - 1) / TILE_M;

    zero_kernel<<<1024, 256>>>();
    mlp_pool<0><<<152, 256, SMEM_DYN>>>(N_BUILD, ntA, x, abc, w1, b1, w2, b2, nullptr);
    mlp_pool<1><<<152, 256, SMEM_DYN>>>(N_CABLE, ntB, nullptr, act, w3, b3, w4, b4, out_cable);
    finalize_trans<<<(N_TRANS * D + 255) / 256, 256>>>(out_trans);
    (void)in_sizes; (void)n_in; (void)out_size;
}

// round 17
// speedup vs baseline: 1.1965x; 1.0711x over previous
#include <cuda_runtime.h>
#include <cuda_fp16.h>
#include <cstdint>

#define N_BUILD 1048576
#define N_CABLE 50000
#define N_TRANS 2000
#define D 128
#define TILE_M 256   // 8 warps x 32 rows, 2 CTAs/SM

// ---------------- device scratch (no allocations allowed) ----------------
__device__ float g_sum_c[N_CABLE * D];
__device__ int   g_cnt_c[N_CABLE];
__device__ float g_sum_t[N_TRANS * D];
__device__ int   g_cnt_t[N_TRANS];

// SMEM: weight tiles [n=128][k=128] fp16, row stride 256B, XOR-swizzled 16B chunks.
#define OFF_WAH 0
#define OFF_WBH 32768
#define OFF_BA  65536
#define OFF_BB  (OFF_BA + 512)
#define SMEM_DYN (OFF_BB + 512 + 1024)

static __device__ __forceinline__ uint32_t smem_u32(const void* p) {
    uint32_t a;
    asm("{ .reg .u64 t; cvta.to.shared.u64 t, %1; cvt.u32.u64 %0, t; }" : "=r"(a) : "l"(p));
    return a;
}
static __device__ __forceinline__ uint32_t pk_h2(float a, float b) {
    __half2 h = __floats2half2_rn(a, b);
    return *(uint32_t*)&h;
}
static __device__ __forceinline__ void ldsm4(uint32_t* r, uint32_t addr) {
    asm volatile("ldmatrix.sync.aligned.m8n8.x4.shared.b16 {%0,%1,%2,%3}, [%4];"
                 : "=r"(r[0]), "=r"(r[1]), "=r"(r[2]), "=r"(r[3]) : "r"(addr));
}
// fp16-accumulate MMA: C/D are 2 packed f16x2 regs
static __device__ __forceinline__ void mma16816h(uint32_t* c, const uint32_t* a, uint32_t b0, uint32_t b1) {
    asm volatile("mma.sync.aligned.m16n8k16.row.col.f16.f16.f16.f16 "
                 "{%0,%1}, {%2,%3,%4,%5}, {%6,%7}, {%0,%1};"
                 : "+r"(c[0]), "+r"(c[1])
                 : "r"(a[0]), "r"(a[1]), "r"(a[2]), "r"(a[3]), "r"(b0), "r"(b1));
}
static __device__ __forceinline__ uint32_t hmax2_zero(uint32_t v) {
    __half2 h = *(__half2*)&v;
    __half2 z = __floats2half2_rn(0.f, 0.f);
    __half2 r = __hmax2(h, z);
    return *(uint32_t*)&r;
}
static __device__ __forceinline__ void red_add_v2(float* p, float a, float b) {
    asm volatile("red.global.add.v2.f32 [%0], {%1, %2};" :: "l"(p), "f"(a), "f"(b) : "memory");
}

// ---------------- zero scratch ----------------
__global__ void zero_kernel() {
    int stride = gridDim.x * blockDim.x;
    int t = blockIdx.x * blockDim.x + threadIdx.x;
    float4 z = make_float4(0.f, 0.f, 0.f, 0.f);
    for (int i = t; i < N_CABLE * D / 4; i += stride) ((float4*)g_sum_c)[i] = z;
    for (int i = t; i < N_TRANS * D / 4; i += stride) ((float4*)g_sum_t)[i] = z;
    for (int i = t; i < N_CABLE; i += stride) g_cnt_c[i] = 0;
    for (int i = t; i < N_TRANS; i += stride) g_cnt_t[i] = 0;
}

// ---------------- fused 2-layer MLP + scatter-add, HMMA fp16 accum, 2 CTAs/SM ----------------
template<int MODE>
__global__ __launch_bounds__(256, 2)
void mlp_pool(int nrows, int ntiles,
              const float* __restrict__ xin, const int* __restrict__ idx,
              const float* __restrict__ wA, const float* __restrict__ bA,
              const float* __restrict__ wB, const float* __restrict__ bB,
              float* __restrict__ out_cable) {
    extern __shared__ char smraw[];
    char* sm = (char*)(((uintptr_t)smraw + 1023) & ~(uintptr_t)1023);
    const uint32_t smU = smem_u32(sm);
    float* bAs = (float*)(sm + OFF_BA);
    float* bBs = (float*)(sm + OFF_BB);

    const int tid  = threadIdx.x;
    const int wid  = tid >> 5;
    const int lane = tid & 31;
    const int q    = lane & 3;
    const int rq   = lane >> 2;

    // ---- convert weights to fp16 (RN), swizzle into smem (once per CTA) ----
    for (int i = tid; i < 2 * 128 * 16; i += 256) {
        int m  = i >> 11;
        int r  = (i >> 4) & 127;
        int kc = i & 15;
        const float* src = (m ? wB : wA) + r * 128 + kc * 8;
        float4 f0 = *(const float4*)(src);
        float4 f1 = *(const float4*)(src + 4);
        uint4 hi;
        hi.x = pk_h2(f0.x, f0.y); hi.y = pk_h2(f0.z, f0.w);
        hi.z = pk_h2(f1.x, f1.y); hi.w = pk_h2(f1.z, f1.w);
        uint32_t off = (uint32_t)(r * 256 + ((kc ^ (r & 7)) << 4));
        *(uint4*)(sm + (m ? OFF_WBH : OFF_WAH) + off) = hi;
    }
    for (int i = tid; i < D; i += 256) { bAs[i] = bA[i]; bBs[i] = bB[i]; }
    __syncthreads();

    float* dst = MODE ? g_sum_t : g_sum_c;
    int*   cnt = MODE ? g_cnt_t : g_cnt_c;

    const int browX = ((lane >> 4) << 3) + (lane & 7);
    const int kb    = (lane >> 3) & 1;

    for (int t = blockIdx.x; t < ntiles; t += gridDim.x) {
        const int base = t * TILE_M + wid * 32;
        int rA[2], rB[2], cidA[2], cidB[2];
        float rcA[2], rcB[2];
        #pragma unroll
        for (int h = 0; h < 2; h++) {
            rA[h] = base + 16 * h + rq;
            rB[h] = rA[h] + 8;
            if (MODE == 0) {
                cidA[h] = (rA[h] < nrows) ? idx[rA[h]] : -1;
                cidB[h] = (rB[h] < nrows) ? idx[rB[h]] : -1;
            } else {
                cidA[h] = (rA[h] < nrows) ? idx[rA[h]] : -1;
                cidB[h] = (rB[h] < nrows) ? idx[rB[h]] : -1;
                rcA[h] = (rA[h] < nrows) ? 1.0f / fmaxf((float)g_cnt_c[rA[h]], 1.0f) : 0.f;
                rcB[h] = (rB[h] < nrows) ? 1.0f / fmaxf((float)g_cnt_c[rB[h]], 1.0f) : 0.f;
            }
        }

        // ================= layer 1 (s-outer, f16 acc, bias-initialized) =================
        // acc16[h][j] = {d0,d1}: d0 = (row rA[h], cols 8j+2q..+1), d1 = (row rB[h], same cols)
        uint32_t acc16[2][16][2];
        #pragma unroll
        for (int j = 0; j < 16; j++) {
            int col0 = 8 * j + 2 * q;
            uint32_t bp = pk_h2(bAs[col0], bAs[col0 + 1]);
            #pragma unroll
            for (int h = 0; h < 2; h++) { acc16[h][j][0] = bp; acc16[h][j][1] = bp; }
        }

        #pragma unroll
        for (int s = 0; s < 8; s++) {
            const int k0 = 16 * s + 2 * q;
            uint32_t ah[2][4];
            #pragma unroll
            for (int h = 0; h < 2; h++) {
                float2 va, vb, vc, vd;
                if (MODE == 0) {
                    const float* p1 = xin + (size_t)rA[h] * D;
                    const float* p2 = xin + (size_t)rB[h] * D;
                    va = *(const float2*)(p1 + k0);
                    vb = *(const float2*)(p2 + k0);
                    vc = *(const float2*)(p1 + k0 + 8);
                    vd = *(const float2*)(p2 + k0 + 8);
                } else {
                    va = vb = vc = vd = make_float2(0.f, 0.f);
                    if (cidA[h] >= 0) {
                        const float* p1 = g_sum_c + (size_t)rA[h] * D;
                        float2 v = *(const float2*)(p1 + k0);
                        va.x = v.x * rcA[h]; va.y = v.y * rcA[h];
                        float2 w = *(const float2*)(p1 + k0 + 8);
                        vc.x = w.x * rcA[h]; vc.y = w.y * rcA[h];
                        *(float2*)(out_cable + (size_t)rA[h] * D + k0) = va;
                        *(float2*)(out_cable + (size_t)rA[h] * D + k0 + 8) = vc;
                    }
                    if (cidB[h] >= 0) {
                        const float* p2 = g_sum_c + (size_t)rB[h] * D;
                        float2 v = *(const float2*)(p2 + k0);
                        vb.x = v.x * rcB[h]; vb.y = v.y * rcB[h];
                        float2 w = *(const float2*)(p2 + k0 + 8);
                        vd.x = w.x * rcB[h]; vd.y = w.y * rcB[h];
                        *(float2*)(out_cable + (size_t)rB[h] * D + k0) = vb;
                        *(float2*)(out_cable + (size_t)rB[h] * D + k0 + 8) = vd;
                    }
                }
                ah[h][0] = pk_h2(va.x, va.y);
                ah[h][1] = pk_h2(vb.x, vb.y);
                ah[h][2] = pk_h2(vc.x, vc.y);
                ah[h][3] = pk_h2(vd.x, vd.y);
            }
            // double-buffered ldsm over g
            uint32_t bh[2][4];
            {
                int brow = browX;
                ldsm4(bh[0], smU + (uint32_t)(brow * 256 + (((2 * s + kb) ^ (brow & 7)) << 4)) + OFF_WAH);
            }
            #pragma unroll
            for (int g = 0; g < 8; g++) {
                if (g < 7) {
                    int brow = 16 * (g + 1) + browX;
                    ldsm4(bh[(g + 1) & 1], smU + (uint32_t)(brow * 256 + (((2 * s + kb) ^ (brow & 7)) << 4)) + OFF_WAH);
                }
                const uint32_t* bb = bh[g & 1];
                #pragma unroll
                for (int h = 0; h < 2; h++) {
                    mma16816h(acc16[h][2*g],   ah[h], bb[0], bb[1]);
                    mma16816h(acc16[h][2*g+1], ah[h], bb[2], bb[3]);
                }
            }
        }

        // ---- transition: relu in place; acc16[h][2s..2s+1] IS the layer-2 A fragment for k-step s ----
        #pragma unroll
        for (int h = 0; h < 2; h++)
            #pragma unroll
            for (int j = 0; j < 16; j++) {
                acc16[h][j][0] = hmax2_zero(acc16[h][j][0]);
                acc16[h][j][1] = hmax2_zero(acc16[h][j][1]);
            }

        // ================= layer 2 (g-outer, f16 acc, bias-init, scatter per chunk) =================
        #pragma unroll
        for (int g = 0; g < 8; g++) {
            uint32_t a2[2][2][2];   // [h][tt][d]
            #pragma unroll
            for (int tt = 0; tt < 2; tt++) {
                int col0 = 16 * g + 8 * tt + 2 * q;
                uint32_t bp = pk_h2(bBs[col0], bBs[col0 + 1]);
                #pragma unroll
                for (int h = 0; h < 2; h++) { a2[h][tt][0] = bp; a2[h][tt][1] = bp; }
            }

            // double-buffered ldsm over s
            uint32_t bh[2][4];
            {
                int brow = 16 * g + browX;
                ldsm4(bh[0], smU + (uint32_t)(brow * 256 + ((kb ^ (brow & 7)) << 4)) + OFF_WBH);
            }
            #pragma unroll
            for (int s = 0; s < 8; s++) {
                int brow = 16 * g + browX;
                if (s < 7) {
                    ldsm4(bh[(s + 1) & 1], smU + (uint32_t)(brow * 256 + (((2 * (s + 1) + kb) ^ (brow & 7)) << 4)) + OFF_WBH);
                }
                const uint32_t* bb = bh[s & 1];
                #pragma unroll
                for (int h = 0; h < 2; h++) {
                    mma16816h(a2[h][0], acc16[h][2*s], bb[0], bb[1]);
                    mma16816h(a2[h][1], acc16[h][2*s], bb[2], bb[3]);
                }
            }
            // scatter cols [16g, 16g+16): every lane red.v2 for both of its rows
            #pragma unroll
            for (int h = 0; h < 2; h++) {
                #pragma unroll
                for (int tt = 0; tt < 2; tt++) {
                    int col0 = 16 * g + 8 * tt + 2 * q;
                    if (cidA[h] >= 0) {
                        float2 f = __half22float2(*(__half2*)&a2[h][tt][0]);
                        red_add_v2(dst + (size_t)cidA[h] * D + col0, f.x, f.y);
                    }
                    if (cidB[h] >= 0) {
                        float2 f = __half22float2(*(__half2*)&a2[h][tt][1]);
                        red_add_v2(dst + (size_t)cidB[h] * D + col0, f.x, f.y);
                    }
                }
            }
        }
        if (q == 0) {
            #pragma unroll
            for (int h = 0; h < 2; h++) {
                if (cidA[h] >= 0) atomicAdd(cnt + cidA[h], 1);
                if (cidB[h] >= 0) atomicAdd(cnt + cidB[h], 1);
            }
        }
    }
}

// ---------------- finalize: x_trans = g_sum_t / max(cnt,1) ----------------
__global__ void finalize_trans(float* __restrict__ out_trans) {
    int i = blockIdx.x * blockDim.x + threadIdx.x;
    if (i < N_TRANS * D) {
        int row = i >> 7;
        float cnt = fmaxf((float)g_cnt_t[row], 1.0f);
        out_trans[i] = g_sum_t[i] / cnt;
    }
}

extern "C" void kernel_launch(void* const* d_in, const int* in_sizes, int n_in,
                              void* d_out, int out_size) {
    const float* x   = (const float*)d_in[0];
    const int*   abc = (const int*)d_in[1];
    const int*   act = (const int*)d_in[2];
    const float* w1  = (const float*)d_in[3];
    const float* b1  = (const float*)d_in[4];
    const float* w2  = (const float*)d_in[5];
    const float* b2  = (const float*)d_in[6];
    const float* w3  = (const float*)d_in[7];
    const float* b3  = (const float*)d_in[8];
    const float* w4  = (const float*)d_in[9];
    const float* b4  = (const float*)d_in[10];

    float* out = (float*)d_out;
    float* out_cable = out;                        // [N_CABLE, D]
    float* out_trans = out + (size_t)N_CABLE * D;  // [N_TRANS, D]

    cudaFuncSetAttribute(mlp_pool<0>, cudaFuncAttributeMaxDynamicSharedMemorySize, SMEM_DYN);
    cudaFuncSetAttribute(mlp_pool<1>, cudaFuncAttributeMaxDynamicSharedMemorySize, SMEM_DYN);

    const int ntA = N_BUILD / TILE_M;                 // 4096
    const int ntB = (N_CABLE + TILE_M - 1) / TILE_M;  // 196

    zero_kernel<<<1024, 256>>>();
    mlp_pool<0><<<304, 256, SMEM_DYN>>>(N_BUILD, ntA, x, abc, w1, b1, w2, b2, nullptr);
    mlp_pool<1><<<304, 256, SMEM_DYN>>>(N_CABLE, ntB, nullptr, act, w3, b3, w4, b4, out_cable);
    finalize_trans<<<(N_TRANS * D + 255) / 256, 256>>>(out_trans);
    (void)in_sizes; (void)n_in; (void)out_size;
}